// round 5
// baseline (speedup 1.0000x reference)
#include <cuda_runtime.h>

#define NB      160            // 5*32 boxes per batch
#define NT      256
#define RSPLIT  16
#define ROWS    32             // stream rows per CTA
#define QROWS   128            // paint rows per CTA (4 quarters)
#define NCTAS   (64 * RSPLIT)

__device__ unsigned g_mask[64][512 * 16];   // full-image bitmasks (2 MB)
__device__ float    g_cnt[64][4];           // painted counts per (batch, quarter)
__device__ float    g_part[64][RSPLIT][2];  // [pred_sum, painted_sigmoid_sum]
__device__ unsigned g_count = 0;            // self-resetting last-CTA counter

__device__ __forceinline__ float sigf(float x) {
    return __fdividef(1.0f, 1.0f + __expf(-x));   // EX2 + RCP
}

// ---------------------------------------------------------------------------
// Kernel 1: paint each batch's mask ONCE (grid 64 x 4 quarters).
// Thread exclusively owns column-word w = tid&15 of rows [8*(tid>>4), +8)
// within its quarter: no atomics, no races. Exact painted count via popc.
// ---------------------------------------------------------------------------
__global__ void __launch_bounds__(NT)
mml_paint(const int* __restrict__ tgt)
{
    const int b  = blockIdx.x;
    const int q  = blockIdx.y;
    const int R0 = q * QROWS;          // global row base of this quarter
    const int tid = threadIdx.x;

    __shared__ unsigned sm[QROWS * 16];   // 8 KB mask tile
    __shared__ int4     boxes[NB];
    __shared__ float    rw[NT / 32];

    for (int i = tid; i < QROWS * 16; i += NT) sm[i] = 0u;
    const int4* tb = (const int4*)(tgt + (size_t)b * NB * 4);
    if (tid < NB) boxes[tid] = tb[tid];
    __syncthreads();

    const int w  = tid & 15;           // column word
    const int r0 = (tid >> 4) * 8;     // local row base (8 rows owned)
    const int cb = w * 32;

    for (int i = 0; i < NB; i++) {
        int4 bx = boxes[i];
        int x1 = min(bx.x, 512),        y1 = min(bx.y, 512);
        int x2 = min(bx.x + bx.z, 512), y2 = min(bx.y + bx.w, 512);
        int lo = min(max(y1 - cb, 0), 32);
        int hi = min(max(y2 - cb, 0), 32);
        unsigned bits = (unsigned)((1ull << hi) - (1ull << lo));
        if (bits == 0u) continue;
        int rs = max(x1 - R0, r0), re = min(x2 - R0, r0 + 8);
        for (int r = rs; r < re; r++) sm[r * 16 + w] |= bits;
    }
    __syncthreads();

    // exact painted-pixel count for this quarter
    unsigned tot = 0;
    #pragma unroll
    for (int r = r0; r < r0 + 8; r++) tot += __popc(sm[r * 16 + w]);
    float c = (float)tot;
    #pragma unroll
    for (int off = 16; off; off >>= 1) c += __shfl_down_sync(0xffffffffu, c, off);
    if ((tid & 31) == 0) rw[tid >> 5] = c;
    __syncthreads();
    if (tid == 0) {
        float s = 0.f;
        #pragma unroll
        for (int i = 0; i < NT / 32; i++) s += rw[i];
        g_cnt[b][q] = s;
    }

    // write mask tile to global (coalesced uint4)
    uint4*       dst = (uint4*)&g_mask[b][R0 * 16];
    const uint4* src = (const uint4*)sm;
    for (int i = tid; i < QROWS * 16 / 4; i += NT) dst[i] = src[i];
}

// ---------------------------------------------------------------------------
// Kernel 2: pure streaming reduction. No painting, no counting.
// ---------------------------------------------------------------------------
__global__ void __launch_bounds__(NT, 5)
mml_stream(const float* __restrict__ pred, float* __restrict__ out)
{
    const int b    = blockIdx.x;
    const int seg  = blockIdx.y;
    const int row0 = seg * ROWS;
    const int tid  = threadIdx.x;
    const int lane = tid & 31;
    const int warp = tid >> 5;

    __shared__ unsigned mask[ROWS * 16];   // 2 KB tile
    __shared__ float    red[2][NT / 32];
    __shared__ float    shl[64];
    __shared__ bool     isLast;

    // copy this CTA's mask tile (128 uint4)
    {
        const uint4* src = (const uint4*)&g_mask[b][row0 * 16];
        uint4*       dst = (uint4*)mask;
        if (tid < ROWS * 16 / 4) dst[tid] = src[tid];
    }
    __syncthreads();

    // streaming loop: stride 256 float4 -> column invariant, row += 2/iter
    float psum = 0.f, isum = 0.f;
    const float4* p = (const float4*)(pred + ((size_t)b * 512 + row0) * 512);
    const int c4   = tid & 127;
    const int wofs = c4 >> 3;
    const int msh  = (c4 & 7) * 4;
    int r = tid >> 7;
    #pragma unroll 4
    for (int k = 0; k < ROWS * 512 / 4 / NT; k++) {
        float4 v = p[tid + NT * k];
        float s0 = sigf(v.x), s1 = sigf(v.y), s2 = sigf(v.z), s3 = sigf(v.w);
        psum += (s0 + s1) + (s2 + s3);
        unsigned mw = (mask[r * 16 + wofs] >> msh) & 0xFu;
        if (mw & 1u) isum += s0;
        if (mw & 2u) isum += s1;
        if (mw & 4u) isum += s2;
        if (mw & 8u) isum += s3;
        r += 2;
    }

    // block reduce
    #pragma unroll
    for (int off = 16; off; off >>= 1) {
        psum += __shfl_down_sync(0xffffffffu, psum, off);
        isum += __shfl_down_sync(0xffffffffu, isum, off);
    }
    if (lane == 0) { red[0][warp] = psum; red[1][warp] = isum; }
    __syncthreads();
    if (tid == 0) {
        float P = 0.f, I = 0.f;
        #pragma unroll
        for (int w = 0; w < NT / 32; w++) { P += red[0][w]; I += red[1][w]; }
        g_part[b][seg][0] = P;
        g_part[b][seg][1] = I;
        __threadfence();
        unsigned prev = atomicAdd(&g_count, 1u);
        isLast = (prev == NCTAS - 1);
        if (isLast) g_count = 0;               // self-reset for graph replay
    }
    __syncthreads();

    // fused final dice reduction in last CTA
    if (isLast) {
        __threadfence();
        if (tid < 64) {
            volatile float* gp = (volatile float*)g_part;
            volatile float* gc = (volatile float*)g_cnt;
            float P = 0.f, I = 0.f, C = 0.f;
            for (int s = 0; s < RSPLIT; s++) {
                P += gp[(tid * RSPLIT + s) * 2 + 0];
                I += gp[(tid * RSPLIT + s) * 2 + 1];
            }
            #pragma unroll
            for (int qq = 0; qq < 4; qq++) C += gc[tid * 4 + qq];
            float inter = 255.f * I;
            shl[tid] = (inter + 1.f) / (P + 255.f * C - inter + 1.f);
        }
        __syncthreads();
        #pragma unroll
        for (int off = 32; off; off >>= 1) {
            if (tid < off && tid + off < 64) shl[tid] += shl[tid + off];
            __syncthreads();
        }
        if (tid == 0) out[0] = 1.0f - shl[0] * (1.0f / 64.0f);
    }
}

extern "C" void kernel_launch(void* const* d_in, const int* in_sizes, int n_in,
                              void* d_out, int out_size) {
    const float* pred = (const float*)d_in[0];   // (64,1,512,512) fp32
    const int*   tgt  = (const int*)d_in[1];     // (64,5,32,4) int32
    float* out = (float*)d_out;                  // scalar

    mml_paint<<<dim3(64, 4), NT>>>(tgt);
    mml_stream<<<dim3(64, RSPLIT), NT>>>(pred, out);
}

// round 6
// speedup vs baseline: 1.4415x; 1.4415x over previous
#include <cuda_runtime.h>

#define NB      160            // 5*32 boxes per batch
#define NT      256
#define PNT     128            // paint threads (1 row each)
#define RSPLIT  16
#define ROWS    32             // stream rows per CTA
#define NCTAS   (64 * RSPLIT)

__device__ unsigned g_mask[64][512 * 16];   // full-image bitmasks (2 MB)
__device__ float    g_cnt[64][4];           // painted counts per (batch, quarter)
__device__ float    g_part[64][RSPLIT][2];  // [pred_sum, painted_sigmoid_sum]
__device__ unsigned g_count = 0;            // self-resetting last-CTA counter

__device__ __forceinline__ float sigf(float x) {
    return __fdividef(1.0f, 1.0f + __expf(-x));   // EX2 + RCP
}

// ---------------------------------------------------------------------------
// Kernel 1: paint. Grid (64,4), 128 threads; thread owns image row q*128+tid.
// Padded smem row (stride 17) -> conflict-free; no atomics; exact count popc.
// ---------------------------------------------------------------------------
__global__ void __launch_bounds__(PNT)
mml_paint(const int* __restrict__ tgt)
{
    const int b   = blockIdx.x;
    const int q   = blockIdx.y;
    const int tid = threadIdx.x;
    const int R   = q * PNT + tid;         // global image row owned

    __shared__ int4     boxes[NB];
    __shared__ unsigned sm[PNT * 17];      // 16 used words + 1 pad per row
    __shared__ float    rw[PNT / 32];

    const int4* tb = (const int4*)(tgt + (size_t)b * NB * 4);
    for (int i = tid; i < NB; i += PNT) boxes[i] = tb[i];
    #pragma unroll
    for (int w = 0; w < 16; w++) sm[tid * 17 + w] = 0u;
    __syncthreads();

    for (int i = 0; i < NB; i++) {
        int4 bx = boxes[i];                 // LDS.128 broadcast
        int x1 = min(bx.x, 512), x2 = min(bx.x + bx.z, 512);
        if (R < x1 || R >= x2) continue;
        int y1 = min(bx.y, 512), y2 = min(bx.y + bx.w, 512);
        if (y2 <= y1) continue;
        int wlo = y1 >> 5, whi = (y2 - 1) >> 5;
        unsigned loMask = ~((1u << (y1 & 31)) - 1u);
        unsigned hiMask = 0xFFFFFFFFu >> (31 - ((y2 - 1) & 31));
        unsigned* mrow = &sm[tid * 17];
        for (int w = wlo; w <= whi; w++) {
            unsigned bits = 0xFFFFFFFFu;
            if (w == wlo) bits &= loMask;
            if (w == whi) bits &= hiMask;
            mrow[w] |= bits;
        }
    }

    // write own row to global + exact popc count (no sync needed: own-row only)
    unsigned tot = 0;
    uint4* dst = (uint4*)&g_mask[b][R * 16];
    #pragma unroll
    for (int j = 0; j < 4; j++) {
        uint4 v = make_uint4(sm[tid * 17 + 4 * j + 0], sm[tid * 17 + 4 * j + 1],
                             sm[tid * 17 + 4 * j + 2], sm[tid * 17 + 4 * j + 3]);
        tot += __popc(v.x) + __popc(v.y) + __popc(v.z) + __popc(v.w);
        dst[j] = v;
    }
    float c = (float)tot;
    #pragma unroll
    for (int off = 16; off; off >>= 1) c += __shfl_down_sync(0xffffffffu, c, off);
    if ((tid & 31) == 0) rw[tid >> 5] = c;
    __syncthreads();
    if (tid == 0) {
        float s = 0.f;
        #pragma unroll
        for (int i = 0; i < PNT / 32; i++) s += rw[i];
        g_cnt[b][q] = s;
    }
}

// ---------------------------------------------------------------------------
// Kernel 2: streaming reduction. Mask nibbles pre-packed into one u64 reg;
// hot loop = LDG.128 + sigmoid + masked adds, unroll 8 for MLP.
// ---------------------------------------------------------------------------
__global__ void __launch_bounds__(NT, 4)
mml_stream(const float* __restrict__ pred, float* __restrict__ out)
{
    const int b    = blockIdx.x;
    const int seg  = blockIdx.y;
    const int row0 = seg * ROWS;
    const int tid  = threadIdx.x;
    const int lane = tid & 31;
    const int warp = tid >> 5;

    __shared__ float red[2][NT / 32];
    __shared__ float shl[64];
    __shared__ bool  isLast;

    // pre-pack this thread's 16 mask nibbles (rows r0base+2k, fixed column)
    const int c4   = tid & 127;
    const int wofs = c4 >> 3;
    const int msh  = (c4 & 7) * 4;
    const int rb   = tid >> 7;                 // 0 or 1
    unsigned long long mbits = 0ull;
    {
        const unsigned* gm = &g_mask[b][(row0 + rb) * 16 + wofs];
        #pragma unroll
        for (int k = 0; k < 16; k++) {
            unsigned nib = (gm[32 * k] >> msh) & 0xFu;   // +2 rows = +32 words
            mbits |= (unsigned long long)nib << (4 * k);
        }
    }

    // streaming loop over this CTA's 32x512 tile
    float psum = 0.f, isum = 0.f;
    const float4* p = (const float4*)(pred + ((size_t)b * 512 + row0) * 512);
    #pragma unroll 8
    for (int k = 0; k < ROWS * 512 / 4 / NT; k++) {
        float4 v = p[tid + NT * k];
        float s0 = sigf(v.x), s1 = sigf(v.y), s2 = sigf(v.z), s3 = sigf(v.w);
        psum += (s0 + s1) + (s2 + s3);
        unsigned mw = (unsigned)(mbits >> (4 * k)) & 0xFu;
        if (mw & 1u) isum += s0;
        if (mw & 2u) isum += s1;
        if (mw & 4u) isum += s2;
        if (mw & 8u) isum += s3;
    }

    // block reduce
    #pragma unroll
    for (int off = 16; off; off >>= 1) {
        psum += __shfl_down_sync(0xffffffffu, psum, off);
        isum += __shfl_down_sync(0xffffffffu, isum, off);
    }
    if (lane == 0) { red[0][warp] = psum; red[1][warp] = isum; }
    __syncthreads();
    if (tid == 0) {
        float P = 0.f, I = 0.f;
        #pragma unroll
        for (int w = 0; w < NT / 32; w++) { P += red[0][w]; I += red[1][w]; }
        g_part[b][seg][0] = P;
        g_part[b][seg][1] = I;
        __threadfence();
        unsigned prev = atomicAdd(&g_count, 1u);
        isLast = (prev == NCTAS - 1);
        if (isLast) g_count = 0;               // self-reset for graph replay
    }
    __syncthreads();

    // fused final dice reduction in last CTA
    if (isLast) {
        __threadfence();
        if (tid < 64) {
            volatile float* gp = (volatile float*)g_part;
            volatile float* gc = (volatile float*)g_cnt;
            float P = 0.f, I = 0.f, C = 0.f;
            for (int s = 0; s < RSPLIT; s++) {
                P += gp[(tid * RSPLIT + s) * 2 + 0];
                I += gp[(tid * RSPLIT + s) * 2 + 1];
            }
            #pragma unroll
            for (int qq = 0; qq < 4; qq++) C += gc[tid * 4 + qq];
            float inter = 255.f * I;
            shl[tid] = (inter + 1.f) / (P + 255.f * C - inter + 1.f);
        }
        __syncthreads();
        #pragma unroll
        for (int off = 32; off; off >>= 1) {
            if (tid < off && tid + off < 64) shl[tid] += shl[tid + off];
            __syncthreads();
        }
        if (tid == 0) out[0] = 1.0f - shl[0] * (1.0f / 64.0f);
    }
}

extern "C" void kernel_launch(void* const* d_in, const int* in_sizes, int n_in,
                              void* d_out, int out_size) {
    const float* pred = (const float*)d_in[0];   // (64,1,512,512) fp32
    const int*   tgt  = (const int*)d_in[1];     // (64,5,32,4) int32
    float* out = (float*)d_out;                  // scalar

    mml_paint<<<dim3(64, 4), PNT>>>(tgt);
    mml_stream<<<dim3(64, RSPLIT), NT>>>(pred, out);
}

// round 8
// speedup vs baseline: 2.4473x; 1.6977x over previous
#include <cuda_runtime.h>

#define NB      160            // 5*32 boxes per batch
#define NT      256
#define RSPLIT  16
#define ROWS    32             // rows per CTA
#define MW      17             // padded mask row stride (words) -> conflict-free
#define NCTAS   (64 * RSPLIT)

__device__ float    g_part[64][RSPLIT][4];  // [pred_sum, painted_sig_sum, count]
__device__ unsigned g_count = 0;            // self-resetting last-CTA counter

__device__ __forceinline__ float sigf(float x) {
    return __fdividef(1.0f, 1.0f + __expf(-x));   // EX2 + RCP
}

__global__ void __launch_bounds__(NT, 6)
mml_fused(const float* __restrict__ pred, const int* __restrict__ tgt,
          float* __restrict__ out)
{
    const int b    = blockIdx.x;
    const int seg  = blockIdx.y;
    const int row0 = seg * ROWS;
    const int tid  = threadIdx.x;
    const int lane = tid & 31;
    const int warp = tid >> 5;

    __shared__ int4     cbox[NB];          // compacted: (r0loc, r1loc, y1, y2)
    __shared__ int      s_nbox;
    __shared__ unsigned sm[ROWS * MW];     // padded mask tile
    __shared__ float    red[3][NT / 32];
    __shared__ float    shl[64];
    __shared__ bool     isLast;

    if (tid == 0) s_nbox = 0;
    for (int i = tid; i < ROWS * MW; i += NT) sm[i] = 0u;
    __syncthreads();

    // ---- compact boxes intersecting this 32-row segment ----
    const int4* tb = (const int4*)(tgt + (size_t)b * NB * 4);
    if (tid < NB) {
        int4 bx = tb[tid];
        int x1 = min(bx.x, 512),        y1 = min(bx.y, 512);
        int x2 = min(bx.x + bx.z, 512), y2 = min(bx.y + bx.w, 512);
        if (x2 > row0 && x1 < row0 + ROWS && y2 > y1) {
            int slot = atomicAdd(&s_nbox, 1);
            cbox[slot] = make_int4(max(x1 - row0, 0), min(x2 - row0, ROWS), y1, y2);
        }
    }
    __syncthreads();
    const int nbox = s_nbox;

    // ---- warp-per-box paint: lane = row, padded stride -> 32 distinct banks ----
    for (int i = warp; i < nbox; i += NT / 32) {
        int4 bx = cbox[i];
        int wlo = bx.z >> 5, whi = (bx.w - 1) >> 5;
        unsigned loMask = ~((1u << (bx.z & 31)) - 1u);
        unsigned hiMask = 0xFFFFFFFFu >> (31 - ((bx.w - 1) & 31));
        int r = bx.x + lane;
        if (r < bx.y) {
            unsigned* mrow = &sm[r * MW];
            for (int w = wlo; w <= whi; w++) {
                unsigned bits = 0xFFFFFFFFu;
                if (w == wlo) bits &= loMask;
                if (w == whi) bits &= hiMask;
                atomicOr(&mrow[w], bits);
            }
        }
    }
    __syncthreads();

    // ---- exact painted count: thread owns cells tid and tid+256 ----
    float cntf;
    {
        int c0 = tid, c1 = tid + NT;
        cntf = (float)(__popc(sm[(c0 >> 4) * MW + (c0 & 15)]) +
                       __popc(sm[(c1 >> 4) * MW + (c1 & 15)]));
    }

    // ---- prepack this thread's 16 mask nibbles into one u64 ----
    const int c4   = tid & 127;
    const int wofs = c4 >> 3;
    const int msh  = (c4 & 7) * 4;
    const int rb   = tid >> 7;                 // 0 or 1
    unsigned long long mbits = 0ull;
    #pragma unroll
    for (int k = 0; k < 16; k++) {
        unsigned nib = (sm[(rb + 2 * k) * MW + wofs] >> msh) & 0xFu;
        mbits |= (unsigned long long)nib << (4 * k);
    }

    // ---- streaming loop: LDG.128 + sigmoid + masked adds only ----
    float psum = 0.f, isum = 0.f;
    const float4* p = (const float4*)(pred + ((size_t)b * 512 + row0) * 512);
    #pragma unroll 4
    for (int k = 0; k < ROWS * 512 / 4 / NT; k++) {
        float4 v = p[tid + NT * k];
        float s0 = sigf(v.x), s1 = sigf(v.y), s2 = sigf(v.z), s3 = sigf(v.w);
        psum += (s0 + s1) + (s2 + s3);
        unsigned mw = (unsigned)(mbits >> (4 * k)) & 0xFu;
        if (mw & 1u) isum += s0;
        if (mw & 2u) isum += s1;
        if (mw & 4u) isum += s2;
        if (mw & 8u) isum += s3;
    }

    // ---- block reduce ----
    #pragma unroll
    for (int off = 16; off; off >>= 1) {
        psum += __shfl_down_sync(0xffffffffu, psum, off);
        isum += __shfl_down_sync(0xffffffffu, isum, off);
        cntf += __shfl_down_sync(0xffffffffu, cntf, off);
    }
    if (lane == 0) { red[0][warp] = psum; red[1][warp] = isum; red[2][warp] = cntf; }
    __syncthreads();
    if (tid == 0) {
        float P = 0.f, I = 0.f, C = 0.f;
        #pragma unroll
        for (int w = 0; w < NT / 32; w++) { P += red[0][w]; I += red[1][w]; C += red[2][w]; }
        g_part[b][seg][0] = P;
        g_part[b][seg][1] = I;
        g_part[b][seg][2] = C;
        __threadfence();
        unsigned prev = atomicAdd(&g_count, 1u);
        isLast = (prev == NCTAS - 1);
        if (isLast) g_count = 0;               // self-reset for graph replay
    }
    __syncthreads();

    // ---- fused final dice reduction in last CTA ----
    if (isLast) {
        __threadfence();
        if (tid < 64) {
            volatile float* gp = (volatile float*)g_part;
            float P = 0.f, I = 0.f, C = 0.f;
            for (int s = 0; s < RSPLIT; s++) {
                P += gp[(tid * RSPLIT + s) * 4 + 0];
                I += gp[(tid * RSPLIT + s) * 4 + 1];
                C += gp[(tid * RSPLIT + s) * 4 + 2];
            }
            float inter = 255.f * I;
            shl[tid] = (inter + 1.f) / (P + 255.f * C - inter + 1.f);
        }
        __syncthreads();
        #pragma unroll
        for (int off = 32; off; off >>= 1) {
            if (tid < off && tid + off < 64) shl[tid] += shl[tid + off];
            __syncthreads();
        }
        if (tid == 0) out[0] = 1.0f - shl[0] * (1.0f / 64.0f);
    }
}

extern "C" void kernel_launch(void* const* d_in, const int* in_sizes, int n_in,
                              void* d_out, int out_size) {
    const float* pred = (const float*)d_in[0];   // (64,1,512,512) fp32
    const int*   tgt  = (const int*)d_in[1];     // (64,5,32,4) int32
    float* out = (float*)d_out;                  // scalar

    mml_fused<<<dim3(64, RSPLIT), NT>>>(pred, tgt, out);
}

// round 9
// speedup vs baseline: 2.6409x; 1.0791x over previous
#include <cuda_runtime.h>

#define NB      160            // 5*32 boxes per batch
#define NT      256
#define RSPLIT  16
#define ROWS    32             // rows per CTA
#define MW      17             // padded mask row stride (words) -> conflict-free
#define NCTAS   (64 * RSPLIT)

__device__ float    g_part[64][RSPLIT][4];  // [tanh_sum, painted_tanh_sum, count]
__device__ unsigned g_count = 0;            // self-resetting last-CTA counter

// hardware tanh: 1 MUFU op (sm_75+)
__device__ __forceinline__ float htanh(float x) {
    float t;
    asm("tanh.approx.f32 %0, %1;" : "=f"(t) : "f"(x));
    return t;
}

__global__ void __launch_bounds__(NT, 6)
mml_fused(const float* __restrict__ pred, const int* __restrict__ tgt,
          float* __restrict__ out)
{
    const int b    = blockIdx.x;
    const int seg  = blockIdx.y;
    const int row0 = seg * ROWS;
    const int tid  = threadIdx.x;
    const int lane = tid & 31;
    const int warp = tid >> 5;

    __shared__ int4     cbox[NB];          // compacted: (r0loc, r1loc, y1, y2)
    __shared__ int      s_nbox;
    __shared__ unsigned sm[ROWS * MW];     // padded mask tile
    __shared__ float    red[3][NT / 32];
    __shared__ float    shl[64];
    __shared__ bool     isLast;

    if (tid == 0) s_nbox = 0;
    for (int i = tid; i < ROWS * MW; i += NT) sm[i] = 0u;
    __syncthreads();

    // ---- compact boxes intersecting this 32-row segment ----
    const int4* tb = (const int4*)(tgt + (size_t)b * NB * 4);
    if (tid < NB) {
        int4 bx = tb[tid];
        int x1 = min(bx.x, 512),        y1 = min(bx.y, 512);
        int x2 = min(bx.x + bx.z, 512), y2 = min(bx.y + bx.w, 512);
        if (x2 > row0 && x1 < row0 + ROWS && y2 > y1) {
            int slot = atomicAdd(&s_nbox, 1);
            cbox[slot] = make_int4(max(x1 - row0, 0), min(x2 - row0, ROWS), y1, y2);
        }
    }
    __syncthreads();
    const int nbox = s_nbox;

    // ---- warp-per-box paint: lane = row, padded stride -> 32 distinct banks ----
    for (int i = warp; i < nbox; i += NT / 32) {
        int4 bx = cbox[i];
        int wlo = bx.z >> 5, whi = (bx.w - 1) >> 5;
        unsigned loMask = ~((1u << (bx.z & 31)) - 1u);
        unsigned hiMask = 0xFFFFFFFFu >> (31 - ((bx.w - 1) & 31));
        int r = bx.x + lane;
        if (r < bx.y) {
            unsigned* mrow = &sm[r * MW];
            for (int w = wlo; w <= whi; w++) {
                unsigned bits = 0xFFFFFFFFu;
                if (w == wlo) bits &= loMask;
                if (w == whi) bits &= hiMask;
                atomicOr(&mrow[w], bits);
            }
        }
    }
    __syncthreads();

    // ---- exact painted count: thread owns cells tid and tid+256 ----
    float cntf;
    {
        int c0 = tid, c1 = tid + NT;
        cntf = (float)(__popc(sm[(c0 >> 4) * MW + (c0 & 15)]) +
                       __popc(sm[(c1 >> 4) * MW + (c1 & 15)]));
    }

    // ---- prepack this thread's 16 mask nibbles into two u32 regs ----
    const int c4   = tid & 127;
    const int wofs = c4 >> 3;
    const int msh  = (c4 & 7) * 4;
    const int rb   = tid >> 7;                 // 0 or 1
    unsigned mlo = 0u, mhi = 0u;
    #pragma unroll
    for (int k = 0; k < 8; k++) {
        mlo |= ((sm[(rb + 2 * k) * MW + wofs] >> msh) & 0xFu) << (4 * k);
        mhi |= ((sm[(rb + 2 * (k + 8)) * MW + wofs] >> msh) & 0xFu) << (4 * k);
    }
    __syncthreads();

    // ---- streaming loop: sigmoid = 0.5*tanh(x/2)+0.5; constants folded out ----
    float tsum = 0.f, tisum = 0.f;
    const float4* p = (const float4*)(pred + ((size_t)b * 512 + row0) * 512);
    #pragma unroll 4
    for (int k = 0; k < ROWS * 512 / 4 / NT; k++) {
        float4 v = p[tid + NT * k];
        float t0 = htanh(0.5f * v.x), t1 = htanh(0.5f * v.y);
        float t2 = htanh(0.5f * v.z), t3 = htanh(0.5f * v.w);
        tsum += (t0 + t1) + (t2 + t3);
        unsigned mw = ((k < 8 ? mlo : mhi) >> (4 * (k & 7))) & 0xFu;
        if (mw & 1u) tisum += t0;
        if (mw & 2u) tisum += t1;
        if (mw & 4u) tisum += t2;
        if (mw & 8u) tisum += t3;
    }

    // ---- block reduce ----
    #pragma unroll
    for (int off = 16; off; off >>= 1) {
        tsum  += __shfl_down_sync(0xffffffffu, tsum,  off);
        tisum += __shfl_down_sync(0xffffffffu, tisum, off);
        cntf  += __shfl_down_sync(0xffffffffu, cntf,  off);
    }
    if (lane == 0) { red[0][warp] = tsum; red[1][warp] = tisum; red[2][warp] = cntf; }
    __syncthreads();
    if (tid == 0) {
        float T = 0.f, TI = 0.f, C = 0.f;
        #pragma unroll
        for (int w = 0; w < NT / 32; w++) { T += red[0][w]; TI += red[1][w]; C += red[2][w]; }
        g_part[b][seg][0] = T;
        g_part[b][seg][1] = TI;
        g_part[b][seg][2] = C;
        __threadfence();
        unsigned prev = atomicAdd(&g_count, 1u);
        isLast = (prev == NCTAS - 1);
        if (isLast) g_count = 0;               // self-reset for graph replay
    }
    __syncthreads();

    // ---- fused final dice reduction in last CTA ----
    if (isLast) {
        __threadfence();
        if (tid < 64) {
            volatile float* gp = (volatile float*)g_part;
            float T = 0.f, TI = 0.f, C = 0.f;
            for (int s = 0; s < RSPLIT; s++) {
                T  += gp[(tid * RSPLIT + s) * 4 + 0];
                TI += gp[(tid * RSPLIT + s) * 4 + 1];
                C  += gp[(tid * RSPLIT + s) * 4 + 2];
            }
            // unfold: P = 0.5*T + 0.5*512*512 ; I = 0.5*TI + 0.5*C
            float P = 0.5f * T + 131072.0f;
            float I = 0.5f * TI + 0.5f * C;
            float inter = 255.f * I;
            shl[tid] = (inter + 1.f) / (P + 255.f * C - inter + 1.f);
        }
        __syncthreads();
        #pragma unroll
        for (int off = 32; off; off >>= 1) {
            if (tid < off && tid + off < 64) shl[tid] += shl[tid + off];
            __syncthreads();
        }
        if (tid == 0) out[0] = 1.0f - shl[0] * (1.0f / 64.0f);
    }
}

extern "C" void kernel_launch(void* const* d_in, const int* in_sizes, int n_in,
                              void* d_out, int out_size) {
    const float* pred = (const float*)d_in[0];   // (64,1,512,512) fp32
    const int*   tgt  = (const int*)d_in[1];     // (64,5,32,4) int32
    float* out = (float*)d_out;                  // scalar

    mml_fused<<<dim3(64, RSPLIT), NT>>>(pred, tgt, out);
}

// round 10
// speedup vs baseline: 2.6717x; 1.0117x over previous
#include <cuda_runtime.h>

#define NB      160            // 5*32 boxes per batch
#define NT      256
#define RSPLIT  16
#define ROWS    32             // rows per CTA
#define MW      17             // padded mask row stride (words) -> conflict-free
#define NCTAS   (64 * RSPLIT)

__device__ float    g_part[64][RSPLIT][4];  // [tanh_sum, painted_tanh_sum, count]
__device__ unsigned g_count = 0;            // self-resetting last-CTA counter

// hardware tanh: 1 MUFU op
__device__ __forceinline__ float htanh(float x) {
    float t;
    asm("tanh.approx.f32 %0, %1;" : "=f"(t) : "f"(x));
    return t;
}

__global__ void __launch_bounds__(NT, 7)
mml_fused(const float* __restrict__ pred, const int* __restrict__ tgt,
          float* __restrict__ out)
{
    const int b    = blockIdx.x;
    const int seg  = blockIdx.y;
    const int row0 = seg * ROWS;
    const int tid  = threadIdx.x;
    const int lane = tid & 31;
    const int warp = tid >> 5;

    __shared__ int4     cbox[NB];          // compacted: (r0loc, r1loc, y1, y2)
    __shared__ int      s_nbox;
    __shared__ unsigned sm[ROWS * MW];     // padded mask tile
    __shared__ float    red[3][NT / 32];
    __shared__ float    shl[64];
    __shared__ bool     isLast;

    // issue the box load first so its GMEM latency overlaps the smem zeroing
    const int4* tb = (const int4*)(tgt + (size_t)b * NB * 4);
    int4 mybox;
    if (tid < NB) mybox = tb[tid];

    if (tid == 0) s_nbox = 0;
    for (int i = tid; i < ROWS * MW; i += NT) sm[i] = 0u;
    __syncthreads();

    // ---- compact boxes intersecting this 32-row segment ----
    if (tid < NB) {
        int x1 = min(mybox.x, 512),            y1 = min(mybox.y, 512);
        int x2 = min(mybox.x + mybox.z, 512),  y2 = min(mybox.y + mybox.w, 512);
        if (x2 > row0 && x1 < row0 + ROWS && y2 > y1) {
            int slot = atomicAdd(&s_nbox, 1);
            cbox[slot] = make_int4(max(x1 - row0, 0), min(x2 - row0, ROWS), y1, y2);
        }
    }
    __syncthreads();
    const int nbox = s_nbox;

    // ---- warp-per-box paint: lane = row, padded stride -> 32 distinct banks ----
    for (int i = warp; i < nbox; i += NT / 32) {
        int4 bx = cbox[i];
        int wlo = bx.z >> 5, whi = (bx.w - 1) >> 5;
        unsigned loMask = ~((1u << (bx.z & 31)) - 1u);
        unsigned hiMask = 0xFFFFFFFFu >> (31 - ((bx.w - 1) & 31));
        int r = bx.x + lane;
        if (r < bx.y) {
            unsigned* mrow = &sm[r * MW];
            for (int w = wlo; w <= whi; w++) {
                unsigned bits = 0xFFFFFFFFu;
                if (w == wlo) bits &= loMask;
                if (w == whi) bits &= hiMask;
                atomicOr(&mrow[w], bits);
            }
        }
    }
    __syncthreads();

    // ---- exact painted count: thread owns cells tid and tid+256 ----
    float cntf;
    {
        int c0 = tid, c1 = tid + NT;
        cntf = (float)(__popc(sm[(c0 >> 4) * MW + (c0 & 15)]) +
                       __popc(sm[(c1 >> 4) * MW + (c1 & 15)]));
    }

    // ---- prepack this thread's 16 mask nibbles into two u32 regs ----
    // (read-only on sm; no further barrier needed before the stream loop)
    const int c4   = tid & 127;
    const int wofs = c4 >> 3;
    const int msh  = (c4 & 7) * 4;
    const int rb   = tid >> 7;                 // 0 or 1
    unsigned mlo = 0u, mhi = 0u;
    #pragma unroll
    for (int k = 0; k < 8; k++) {
        mlo |= ((sm[(rb + 2 * k) * MW + wofs] >> msh) & 0xFu) << (4 * k);
        mhi |= ((sm[(rb + 2 * (k + 8)) * MW + wofs] >> msh) & 0xFu) << (4 * k);
    }

    // ---- streaming loop: sigmoid = 0.5*tanh(x/2)+0.5; constants folded out ----
    float tsum = 0.f, tisum = 0.f;
    const float4* p = (const float4*)(pred + ((size_t)b * 512 + row0) * 512);
    #pragma unroll 4
    for (int k = 0; k < ROWS * 512 / 4 / NT; k++) {
        float4 v = p[tid + NT * k];
        float t0 = htanh(0.5f * v.x), t1 = htanh(0.5f * v.y);
        float t2 = htanh(0.5f * v.z), t3 = htanh(0.5f * v.w);
        tsum += (t0 + t1) + (t2 + t3);
        unsigned mw = ((k < 8 ? mlo : mhi) >> (4 * (k & 7))) & 0xFu;
        if (mw & 1u) tisum += t0;
        if (mw & 2u) tisum += t1;
        if (mw & 4u) tisum += t2;
        if (mw & 8u) tisum += t3;
    }

    // ---- block reduce ----
    #pragma unroll
    for (int off = 16; off; off >>= 1) {
        tsum  += __shfl_down_sync(0xffffffffu, tsum,  off);
        tisum += __shfl_down_sync(0xffffffffu, tisum, off);
        cntf  += __shfl_down_sync(0xffffffffu, cntf,  off);
    }
    if (lane == 0) { red[0][warp] = tsum; red[1][warp] = tisum; red[2][warp] = cntf; }
    __syncthreads();
    if (tid == 0) {
        float T = 0.f, TI = 0.f, C = 0.f;
        #pragma unroll
        for (int w = 0; w < NT / 32; w++) { T += red[0][w]; TI += red[1][w]; C += red[2][w]; }
        g_part[b][seg][0] = T;
        g_part[b][seg][1] = TI;
        g_part[b][seg][2] = C;
        __threadfence();
        unsigned prev = atomicAdd(&g_count, 1u);
        isLast = (prev == NCTAS - 1);
        if (isLast) g_count = 0;               // self-reset for graph replay
    }
    __syncthreads();

    // ---- fused final dice reduction in last CTA ----
    if (isLast) {
        __threadfence();
        if (tid < 64) {
            volatile float* gp = (volatile float*)g_part;
            float T = 0.f, TI = 0.f, C = 0.f;
            for (int s = 0; s < RSPLIT; s++) {
                T  += gp[(tid * RSPLIT + s) * 4 + 0];
                TI += gp[(tid * RSPLIT + s) * 4 + 1];
                C  += gp[(tid * RSPLIT + s) * 4 + 2];
            }
            // unfold: P = 0.5*T + 0.5*512*512 ; I = 0.5*TI + 0.5*C
            float P = 0.5f * T + 131072.0f;
            float I = 0.5f * TI + 0.5f * C;
            float inter = 255.f * I;
            shl[tid] = (inter + 1.f) / (P + 255.f * C - inter + 1.f);
        }
        __syncthreads();
        #pragma unroll
        for (int off = 32; off; off >>= 1) {
            if (tid < off && tid + off < 64) shl[tid] += shl[tid + off];
            __syncthreads();
        }
        if (tid == 0) out[0] = 1.0f - shl[0] * (1.0f / 64.0f);
    }
}

extern "C" void kernel_launch(void* const* d_in, const int* in_sizes, int n_in,
                              void* d_out, int out_size) {
    const float* pred = (const float*)d_in[0];   // (64,1,512,512) fp32
    const int*   tgt  = (const int*)d_in[1];     // (64,5,32,4) int32
    float* out = (float*)d_out;                  // scalar

    mml_fused<<<dim3(64, RSPLIT), NT>>>(pred, tgt, out);
}